// round 1
// baseline (speedup 1.0000x reference)
#include <cuda_runtime.h>

// GlobalFilter: out = irfft2( rfft2(x, ortho) * W, ortho ) over 16x16 spatial grid,
// per channel. Reduced to: column-DFT (real->9 complex bins), per-(c,v) complex
// 16-tap circular convolution over rows (kernel mu precomputed from W), then
// real inverse column transform with m_v weighting.
//
// x:   [128, 256, 768] f32  (B, N=16*16, C), C contiguous
// W:   [16, 9, 768, 2] f32
// out: [128, 256, 768] f32

#define PP   16
#define NV   9
#define CT   16          // channels per block tile
#define CCH  768
#define BB   128
#define NCT  (CCH / CT)  // 48 channel tiles

// mu layout: [ct][v][d][cl]  (ct = c>>4, cl = c&15) -> coalesced block loads
__device__ float2 g_mu[CCH * NV * PP];

__constant__ float d_COS16[16] = {
    1.0f,  0.9238795325112867f,  0.7071067811865476f,  0.3826834323650898f,
    0.0f, -0.3826834323650898f, -0.7071067811865476f, -0.9238795325112867f,
   -1.0f, -0.9238795325112867f, -0.7071067811865476f, -0.3826834323650898f,
    0.0f,  0.3826834323650898f,  0.7071067811865476f,  0.9238795325112867f};
__constant__ float d_SIN16[16] = {
    0.0f,  0.3826834323650898f,  0.7071067811865476f,  0.9238795325112867f,
    1.0f,  0.9238795325112867f,  0.7071067811865476f,  0.3826834323650898f,
    0.0f, -0.3826834323650898f, -0.7071067811865476f, -0.9238795325112867f,
   -1.0f, -0.9238795325112867f, -0.7071067811865476f, -0.3826834323650898f};

// Compile-time trig (folds to FFMA immediates in fully-unrolled loops)
__host__ __device__ __forceinline__ constexpr float C16(int k) {
    return (k % 16 == 0)  ?  1.0f :
           (k % 16 == 1)  ?  0.9238795325112867f :
           (k % 16 == 2)  ?  0.7071067811865476f :
           (k % 16 == 3)  ?  0.3826834323650898f :
           (k % 16 == 4)  ?  0.0f :
           (k % 16 == 5)  ? -0.3826834323650898f :
           (k % 16 == 6)  ? -0.7071067811865476f :
           (k % 16 == 7)  ? -0.9238795325112867f :
           (k % 16 == 8)  ? -1.0f :
           (k % 16 == 9)  ? -0.9238795325112867f :
           (k % 16 == 10) ? -0.7071067811865476f :
           (k % 16 == 11) ? -0.3826834323650898f :
           (k % 16 == 12) ?  0.0f :
           (k % 16 == 13) ?  0.3826834323650898f :
           (k % 16 == 14) ?  0.7071067811865476f :
                             0.9238795325112867f;
}
__host__ __device__ __forceinline__ constexpr float S16(int k) {
    return C16((k % 16 + 12));   // sin(th) = cos(th - pi/2) -> shift by -4 mod 16 == +12
}

// ---------------------------------------------------------------------------
// K1: mu[c][v][d] = (m_v/256) * sum_u W[u,v,c] * e^{+2*pi*i*u*d/16}
// ---------------------------------------------------------------------------
__global__ void gf_prep(const float* __restrict__ w) {
    int tid = blockIdx.x * blockDim.x + threadIdx.x;
    if (tid >= CCH * NV * PP) return;
    int c   = tid / (NV * PP);
    int rem = tid - c * (NV * PP);
    int v   = rem / PP;
    int d   = rem - v * PP;

    float re = 0.0f, im = 0.0f;
#pragma unroll
    for (int u = 0; u < 16; u++) {
        int iw   = ((u * NV + v) * CCH + c) * 2;
        float wr = w[iw];
        float wi = w[iw + 1];
        int k    = (u * d) & 15;
        float cs = d_COS16[k];
        float sn = d_SIN16[k];
        re = fmaf(wr, cs, fmaf(-wi, sn, re));
        im = fmaf(wr, sn, fmaf( wi, cs, im));
    }
    float scale = ((v == 0) || (v == 8)) ? (1.0f / 256.0f) : (2.0f / 256.0f);
    int ct = c >> 4;
    int cl = c & 15;
    g_mu[(ct * NV * PP + v * PP + d) * CT + cl] = make_float2(re * scale, im * scale);
}

// ---------------------------------------------------------------------------
// K2: fused column-DFT -> complex row circular conv -> inverse column pass
// block: 256 threads = 16 channels x 16 rows; grid: (48 channel-tiles, 128 batches)
// ---------------------------------------------------------------------------
__global__ void __launch_bounds__(256) gf_main(const float* __restrict__ x,
                                               float* __restrict__ out) {
    __shared__ float2 mu_s[NV * PP * CT];   // [v][d][c]
    __shared__ float2 xc_s[PP * NV * CT];   // [p][v][c]

    int b   = blockIdx.y;
    int tid = threadIdx.x;
    int c   = tid & (CT - 1);
    int r   = tid >> 4;                     // p in phase 1, s in phases 2/3
    int c0  = blockIdx.x * CT;

    // stage mu for this channel tile (coalesced; mu lives in L2 after K1)
    {
        const float2* mg = g_mu + blockIdx.x * (NV * PP * CT);
#pragma unroll
        for (int i = 0; i < (NV * PP * CT) / 256; i++)
            mu_s[tid + i * 256] = mg[tid + i * 256];
        // NV*PP*CT = 2304, 2304/256 = 9 exact
    }

    // ---- Phase 1: column DFT, real input -> 9 complex bins per row ----
    float xr[16];
    {
        const float* xp = x + ((size_t)(b * 256 + r * 16) * CCH + c0 + c);
#pragma unroll
        for (int t = 0; t < 16; t++) xr[t] = xp[(size_t)t * CCH];
    }
#pragma unroll
    for (int v = 0; v < NV; v++) {
        float re = 0.0f, im = 0.0f;
#pragma unroll
        for (int t = 0; t < 16; t++) {
            re = fmaf(xr[t],  C16(v * t), re);
            im = fmaf(xr[t], -S16(v * t), im);
        }
        xc_s[(r * NV + v) * CT + c] = make_float2(re, im);
    }
    __syncthreads();

    // ---- Phase 2: per-(c,v) complex circular conv over rows ----
    float2 T[NV];
#pragma unroll
    for (int v = 0; v < NV; v++) T[v] = make_float2(0.0f, 0.0f);

#pragma unroll
    for (int p = 0; p < 16; p++) {
        int d = (r - p) & 15;
#pragma unroll
        for (int v = 0; v < NV; v++) {
            float2 m = mu_s[(v * PP + d) * CT + c];
            float2 X = xc_s[(p * NV + v) * CT + c];
            T[v].x = fmaf(m.x, X.x, fmaf(-m.y, X.y, T[v].x));
            T[v].y = fmaf(m.x, X.y, fmaf( m.y, X.x, T[v].y));
        }
    }

    // ---- Phase 3: inverse column pass (m_v and 1/256 already folded in mu) ----
    {
        float* op = out + ((size_t)(b * 256 + r * 16) * CCH + c0 + c);
#pragma unroll
        for (int t = 0; t < 16; t++) {
            float o = 0.0f;
#pragma unroll
            for (int v = 0; v < NV; v++) {
                o = fmaf(T[v].x,  C16(v * t), o);
                o = fmaf(T[v].y, -S16(v * t), o);
            }
            op[(size_t)t * CCH] = o;
        }
    }
}

// ---------------------------------------------------------------------------
extern "C" void kernel_launch(void* const* d_in, const int* in_sizes, int n_in,
                              void* d_out, int out_size) {
    const float* x = (const float*)d_in[0];
    const float* w = (const float*)d_in[1];
    float* out     = (float*)d_out;
    (void)in_sizes; (void)n_in; (void)out_size;

    gf_prep<<<(CCH * NV * PP + 255) / 256, 256>>>(w);

    dim3 grid(NCT, BB);
    gf_main<<<grid, 256>>>(x, out);
}

// round 2
// speedup vs baseline: 1.2725x; 1.2725x over previous
#include <cuda_runtime.h>
#include <cstdint>

// GlobalFilter: out = irfft2( rfft2(x, ortho) * W, ortho ) over 16x16 per channel.
// Decomposition:
//   Phase 1: column DFT (real -> 9 complex bins) per row            [thread = (p, c)]
//   Phase 2: per-(c,v) complex 16-tap circular conv over rows       [thread = (c, v)]
//            -- all 16 outputs T[s] register-resident, f32x2 FMA
//   Phase 3: real inverse column transform                          [thread = (s, c)]
//
// x:   [128, 256, 768] f32 ; W: [16, 9, 768, 2] f32 ; out: [128, 256, 768] f32

#define PP   16
#define NV   9
#define CT   16
#define CCH  768
#define BB   128
#define NCT  (CCH / CT)

// packed duplicated filter taps:
//   muA[ct][v][d][cl] = (re, re) * scale ; muB = (-im, im) * scale
__device__ float2 g_muA[CCH * NV * PP];
__device__ float2 g_muB[CCH * NV * PP];

__constant__ float d_COS16[16] = {
    1.0f,  0.9238795325112867f,  0.7071067811865476f,  0.3826834323650898f,
    0.0f, -0.3826834323650898f, -0.7071067811865476f, -0.9238795325112867f,
   -1.0f, -0.9238795325112867f, -0.7071067811865476f, -0.3826834323650898f,
    0.0f,  0.3826834323650898f,  0.7071067811865476f,  0.9238795325112867f};
__constant__ float d_SIN16[16] = {
    0.0f,  0.3826834323650898f,  0.7071067811865476f,  0.9238795325112867f,
    1.0f,  0.9238795325112867f,  0.7071067811865476f,  0.3826834323650898f,
    0.0f, -0.3826834323650898f, -0.7071067811865476f, -0.9238795325112867f,
   -1.0f, -0.9238795325112867f, -0.7071067811865476f, -0.3826834323650898f};

__host__ __device__ __forceinline__ constexpr float C16(int k) {
    return (k % 16 == 0)  ?  1.0f :
           (k % 16 == 1)  ?  0.9238795325112867f :
           (k % 16 == 2)  ?  0.7071067811865476f :
           (k % 16 == 3)  ?  0.3826834323650898f :
           (k % 16 == 4)  ?  0.0f :
           (k % 16 == 5)  ? -0.3826834323650898f :
           (k % 16 == 6)  ? -0.7071067811865476f :
           (k % 16 == 7)  ? -0.9238795325112867f :
           (k % 16 == 8)  ? -1.0f :
           (k % 16 == 9)  ? -0.9238795325112867f :
           (k % 16 == 10) ? -0.7071067811865476f :
           (k % 16 == 11) ? -0.3826834323650898f :
           (k % 16 == 12) ?  0.0f :
           (k % 16 == 13) ?  0.3826834323650898f :
           (k % 16 == 14) ?  0.7071067811865476f :
                             0.9238795325112867f;
}
__host__ __device__ __forceinline__ constexpr float S16(int k) {
    return C16(k % 16 + 12);
}

__device__ __forceinline__ uint64_t pack2(float lo, float hi) {
    uint64_t r;
    asm("mov.b64 %0, {%1, %2};" : "=l"(r) : "f"(lo), "f"(hi));
    return r;
}
__device__ __forceinline__ void unpack2(uint64_t v, float& lo, float& hi) {
    asm("mov.b64 {%0, %1}, %2;" : "=f"(lo), "=f"(hi) : "l"(v));
}
__device__ __forceinline__ uint64_t fma2(uint64_t a, uint64_t b, uint64_t c) {
    uint64_t r;
    asm("fma.rn.f32x2 %0, %1, %2, %3;" : "=l"(r) : "l"(a), "l"(b), "l"(c));
    return r;
}

// ---------------------------------------------------------------------------
// K1: mu[c][v][d] = (m_v/256) * sum_u W[u,v,c] * e^{+2 pi i u d/16}; store packed
// ---------------------------------------------------------------------------
__global__ void gf_prep(const float* __restrict__ w) {
    int tid = blockIdx.x * blockDim.x + threadIdx.x;
    if (tid >= CCH * NV * PP) return;
    int c   = tid / (NV * PP);
    int rem = tid - c * (NV * PP);
    int v   = rem / PP;
    int d   = rem - v * PP;

    float re = 0.0f, im = 0.0f;
#pragma unroll
    for (int u = 0; u < 16; u++) {
        int iw   = ((u * NV + v) * CCH + c) * 2;
        float wr = w[iw];
        float wi = w[iw + 1];
        int k    = (u * d) & 15;
        float cs = d_COS16[k];
        float sn = d_SIN16[k];
        re = fmaf(wr, cs, fmaf(-wi, sn, re));
        im = fmaf(wr, sn, fmaf( wi, cs, im));
    }
    float scale = ((v == 0) || (v == 8)) ? (1.0f / 256.0f) : (2.0f / 256.0f);
    re *= scale; im *= scale;
    int ct = c >> 4;
    int cl = c & 15;
    int idx = ((ct * NV + v) * PP + d) * CT + cl;
    g_muA[idx] = make_float2(re, re);
    g_muB[idx] = make_float2(-im, im);
}

// ---------------------------------------------------------------------------
// K2: fused pipeline. block = 256 thr, grid (48 c-tiles, 128 batches)
// ---------------------------------------------------------------------------
__global__ void __launch_bounds__(256, 2) gf_main(const float* __restrict__ x,
                                                  float* __restrict__ out) {
    __shared__ float2 xc_s[NV * PP * CT];   // [v][p][c]
    __shared__ float2 T_s [NV * PP * CT];   // [v][s][c]

    int b   = blockIdx.y;
    int tid = threadIdx.x;
    int c   = tid & (CT - 1);
    int r   = tid >> 4;                     // p (ph1) / s (ph3)
    int c0  = blockIdx.x * CT;

    // ---- Phase 1: column DFT, real -> 9 complex bins per row ----
    {
        float xr[16];
        const float* xp = x + ((size_t)(b * 256 + r * 16) * CCH + c0 + c);
#pragma unroll
        for (int t = 0; t < 16; t++) xr[t] = xp[(size_t)t * CCH];
#pragma unroll
        for (int v = 0; v < NV; v++) {
            float re = 0.0f, im = 0.0f;
#pragma unroll
            for (int t = 0; t < 16; t++) {
                re = fmaf(xr[t],  C16(v * t), re);
                im = fmaf(xr[t], -S16(v * t), im);
            }
            xc_s[(v * PP + r) * CT + c] = make_float2(re, im);
        }
    }
    __syncthreads();

    // ---- Phase 2: per-(c,v) circular conv, 16 outputs register-resident ----
    if (tid < CT * NV) {
        int cc = tid & (CT - 1);
        int v  = tid >> 4;                  // 0..8

        // all 16 filter taps in registers (packed dup form)
        uint64_t muA[16], muB[16];
        {
            const uint64_t* mA = reinterpret_cast<const uint64_t*>(g_muA)
                               + ((blockIdx.x * NV + v) * PP) * CT + cc;
            const uint64_t* mB = reinterpret_cast<const uint64_t*>(g_muB)
                               + ((blockIdx.x * NV + v) * PP) * CT + cc;
#pragma unroll
            for (int d = 0; d < 16; d++) {
                muA[d] = mA[d * CT];
                muB[d] = mB[d * CT];
            }
        }

        uint64_t T[16];
#pragma unroll
        for (int s = 0; s < 16; s++) T[s] = pack2(0.0f, 0.0f);

#pragma unroll
        for (int p = 0; p < 16; p++) {
            float2 X = xc_s[(v * PP + p) * CT + cc];
            uint64_t XP = pack2(X.x, X.y);
            uint64_t XS = pack2(X.y, X.x);
#pragma unroll
            for (int s = 0; s < 16; s++) {
                int d = (s - p) & 15;
                T[s] = fma2(muA[d], XP, T[s]);   // (+re*xr, +re*xi)
                T[s] = fma2(muB[d], XS, T[s]);   // (-im*xi, +im*xr)
            }
        }

#pragma unroll
        for (int s = 0; s < 16; s++) {
            float tx, ty;
            unpack2(T[s], tx, ty);
            T_s[(v * PP + s) * CT + cc] = make_float2(tx, ty);
        }
    }
    __syncthreads();

    // ---- Phase 3: inverse column transform (all scaling folded in mu) ----
    {
        float2 Tv[NV];
#pragma unroll
        for (int v = 0; v < NV; v++) Tv[v] = T_s[(v * PP + r) * CT + c];

        float* op = out + ((size_t)(b * 256 + r * 16) * CCH + c0 + c);
#pragma unroll
        for (int t = 0; t < 16; t++) {
            float o = 0.0f;
#pragma unroll
            for (int v = 0; v < NV; v++) {
                o = fmaf(Tv[v].x,  C16(v * t), o);
                o = fmaf(Tv[v].y, -S16(v * t), o);
            }
            op[(size_t)t * CCH] = o;
        }
    }
}

// ---------------------------------------------------------------------------
extern "C" void kernel_launch(void* const* d_in, const int* in_sizes, int n_in,
                              void* d_out, int out_size) {
    const float* x = (const float*)d_in[0];
    const float* w = (const float*)d_in[1];
    float* out     = (float*)d_out;
    (void)in_sizes; (void)n_in; (void)out_size;

    gf_prep<<<(CCH * NV * PP + 255) / 256, 256>>>(w);

    dim3 grid(NCT, BB);
    gf_main<<<grid, 256>>>(x, out);
}

// round 3
// speedup vs baseline: 1.9372x; 1.5223x over previous
#include <cuda_runtime.h>
#include <cstdint>

// GlobalFilter: out = irfft2( rfft2(x,ortho) * W, ortho ), 16x16 spatial, per channel.
//   Ph1: column rDFT over t (radix-2 folded, FFMA-imm)        thread=(c32, 2 rows)
//   Ph2: per-(c,v) complex circular conv over rows            thread=(c32, vgroup) -- 256 thr exact
//        v=1..7 complex (f32x2), v={0,8} packed real pair
//   Ph3: inverse column pass (radix-2 folded)                 thread=(c32, 2 rows)
//
// x: [128,256,768] f32 ; W: [16,9,768,2] f32 ; out: [128,256,768] f32

#define PP    16
#define NV    9
#define CT    32
#define CCH   768
#define NCT   (CCH / CT)   // 24

// complex taps v=1..7: [ct][v-1][d][c32], packed dup: A=(re,re)*s, B=(-im,im)*s
__device__ float2 g_muA[NCT * 7 * PP * CT];
__device__ float2 g_muB[NCT * 7 * PP * CT];
// real taps for v=0 / v=8: [ct][d][c32] -> (mu0.re, mu8.re) * s
__device__ float2 g_muR[NCT * PP * CT];

__constant__ float d_COS16[16] = {
    1.0f,  0.9238795325112867f,  0.7071067811865476f,  0.3826834323650898f,
    0.0f, -0.3826834323650898f, -0.7071067811865476f, -0.9238795325112867f,
   -1.0f, -0.9238795325112867f, -0.7071067811865476f, -0.3826834323650898f,
    0.0f,  0.3826834323650898f,  0.7071067811865476f,  0.9238795325112867f};
__constant__ float d_SIN16[16] = {
    0.0f,  0.3826834323650898f,  0.7071067811865476f,  0.9238795325112867f,
    1.0f,  0.9238795325112867f,  0.7071067811865476f,  0.3826834323650898f,
    0.0f, -0.3826834323650898f, -0.7071067811865476f, -0.9238795325112867f,
   -1.0f, -0.9238795325112867f, -0.7071067811865476f, -0.3826834323650898f};

__host__ __device__ __forceinline__ constexpr float C16(int k) {
    return (k % 16 == 0)  ?  1.0f :
           (k % 16 == 1)  ?  0.9238795325112867f :
           (k % 16 == 2)  ?  0.7071067811865476f :
           (k % 16 == 3)  ?  0.3826834323650898f :
           (k % 16 == 4)  ?  0.0f :
           (k % 16 == 5)  ? -0.3826834323650898f :
           (k % 16 == 6)  ? -0.7071067811865476f :
           (k % 16 == 7)  ? -0.9238795325112867f :
           (k % 16 == 8)  ? -1.0f :
           (k % 16 == 9)  ? -0.9238795325112867f :
           (k % 16 == 10) ? -0.7071067811865476f :
           (k % 16 == 11) ? -0.3826834323650898f :
           (k % 16 == 12) ?  0.0f :
           (k % 16 == 13) ?  0.3826834323650898f :
           (k % 16 == 14) ?  0.7071067811865476f :
                             0.9238795325112867f;
}
__host__ __device__ __forceinline__ constexpr float S16(int k) {
    return C16(k % 16 + 12);
}

__device__ __forceinline__ uint64_t pack2(float lo, float hi) {
    uint64_t r;
    asm("mov.b64 %0, {%1, %2};" : "=l"(r) : "f"(lo), "f"(hi));
    return r;
}
__device__ __forceinline__ void unpack2(uint64_t v, float& lo, float& hi) {
    asm("mov.b64 {%0, %1}, %2;" : "=f"(lo), "=f"(hi) : "l"(v));
}
__device__ __forceinline__ uint64_t fma2(uint64_t a, uint64_t b, uint64_t c) {
    uint64_t r;
    asm("fma.rn.f32x2 %0, %1, %2, %3;" : "=l"(r) : "l"(a), "l"(b), "l"(c));
    return r;
}

// ---------------------------------------------------------------------------
// K1: mu[c][v][d] = (m_v/256) * sum_u W[u,v,c] e^{+2 pi i u d /16}
// ---------------------------------------------------------------------------
__global__ void gf_prep(const float* __restrict__ w) {
    int tid = blockIdx.x * blockDim.x + threadIdx.x;
    if (tid >= CCH * NV * PP) return;
    int c   = tid / (NV * PP);
    int rem = tid - c * (NV * PP);
    int v   = rem / PP;
    int d   = rem - v * PP;

    float re = 0.0f, im = 0.0f;
#pragma unroll
    for (int u = 0; u < 16; u++) {
        int iw   = ((u * NV + v) * CCH + c) * 2;
        float wr = w[iw];
        float wi = w[iw + 1];
        int k    = (u * d) & 15;
        float cs = d_COS16[k];
        float sn = d_SIN16[k];
        re = fmaf(wr, cs, fmaf(-wi, sn, re));
        im = fmaf(wr, sn, fmaf( wi, cs, im));
    }
    int ct = c >> 5;
    int cl = c & (CT - 1);
    if (v == 0) {
        g_muR[(ct * PP + d) * CT + cl].x = re * (1.0f / 256.0f);
    } else if (v == 8) {
        g_muR[(ct * PP + d) * CT + cl].y = re * (1.0f / 256.0f);
    } else {
        float s = 2.0f / 256.0f;
        int idx = ((ct * 7 + (v - 1)) * PP + d) * CT + cl;
        g_muA[idx] = make_float2(re * s,  re * s);
        g_muB[idx] = make_float2(-im * s, im * s);
    }
}

// ---------------------------------------------------------------------------
// K2: block 256 thr, grid (24 c-tiles, 64 batch-pairs), 2 batches per block
// ---------------------------------------------------------------------------
__global__ void __launch_bounds__(256, 2) gf_main(const float* __restrict__ x,
                                                  float* __restrict__ out) {
    __shared__ float2 spec[NV * PP * CT];   // [v][p][c], reused in-place for T

    int tid = threadIdx.x;
    int c   = tid & (CT - 1);
    int r   = tid >> 5;                     // 0..7 ; rows r and r+8
    int c0  = blockIdx.x * CT;

    // phase-2 identity
    int cc = c;
    int vg = r;                             // 0 -> packed real (v0,v8); 1..7 -> complex v=vg

    // --- preload filter taps into registers (reused for both batches) ---
    uint64_t muA[16], muB[16];
    if (vg == 0) {
        const uint64_t* mR = reinterpret_cast<const uint64_t*>(g_muR)
                           + (blockIdx.x * PP) * CT + cc;
#pragma unroll
        for (int d = 0; d < 16; d++) muA[d] = mR[d * CT];
    } else {
        const uint64_t* mA = reinterpret_cast<const uint64_t*>(g_muA)
                           + ((blockIdx.x * 7 + vg - 1) * PP) * CT + cc;
        const uint64_t* mB = reinterpret_cast<const uint64_t*>(g_muB)
                           + ((blockIdx.x * 7 + vg - 1) * PP) * CT + cc;
#pragma unroll
        for (int d = 0; d < 16; d++) { muA[d] = mA[d * CT]; muB[d] = mB[d * CT]; }
    }

    for (int bi = 0; bi < 2; bi++) {
        int b = blockIdx.y * 2 + bi;

        // ---- Phase 1: column rDFT over t, radix-2 folded, rows r and r+8 ----
        {
            float xr0[16], xr1[16];
            const float* xp0 = x + ((size_t)(b * 256 + r * 16) * CCH + c0 + c);
            const float* xp1 = xp0 + (size_t)8 * 16 * CCH;
#pragma unroll
            for (int t = 0; t < 16; t++) xr0[t] = xp0[(size_t)t * CCH];
#pragma unroll
            for (int t = 0; t < 16; t++) xr1[t] = xp1[(size_t)t * CCH];

#pragma unroll
            for (int row = 0; row < 2; row++) {
                float* xr = row ? xr1 : xr0;
                int rr = r + row * 8;
                float s[8], dd[8];
#pragma unroll
                for (int t = 0; t < 8; t++) { s[t] = xr[t] + xr[t + 8]; dd[t] = xr[t] - xr[t + 8]; }
                // v = 0
                {
                    float re = s[0] + s[1] + s[2] + s[3] + s[4] + s[5] + s[6] + s[7];
                    spec[(0 * PP + rr) * CT + c] = make_float2(re, 0.0f);
                }
                // v = 8: coef (-1)^t
                {
                    float re = s[0] - s[1] + s[2] - s[3] + s[4] - s[5] + s[6] - s[7];
                    spec[(8 * PP + rr) * CT + c] = make_float2(re, 0.0f);
                }
                // even v = 2,4,6 use s ; odd v = 1,3,5,7 use dd
#pragma unroll
                for (int v = 1; v < 8; v++) {
                    const float* src = (v & 1) ? dd : s;
                    float re = 0.0f, im = 0.0f;
#pragma unroll
                    for (int t = 0; t < 8; t++) {
                        re = fmaf(src[t],  C16(v * t), re);
                        im = fmaf(src[t], -S16(v * t), im);
                    }
                    spec[(v * PP + rr) * CT + c] = make_float2(re, im);
                }
            }
        }
        __syncthreads();

        // ---- Phase 2: circular conv over rows; all 256 threads busy ----
        if (vg == 0) {
            // packed real convs for v=0 (lane lo) and v=8 (lane hi)
            uint64_t T[16];
#pragma unroll
            for (int s = 0; s < 16; s++) T[s] = pack2(0.0f, 0.0f);
#pragma unroll
            for (int p = 0; p < 16; p++) {
                float x0 = spec[(0 * PP + p) * CT + cc].x;
                float x8 = spec[(8 * PP + p) * CT + cc].x;
                uint64_t XR = pack2(x0, x8);
#pragma unroll
                for (int s = 0; s < 16; s++)
                    T[s] = fma2(muA[(s - p) & 15], XR, T[s]);
            }
#pragma unroll
            for (int s = 0; s < 16; s++) {
                float t0, t8;
                unpack2(T[s], t0, t8);
                spec[(0 * PP + s) * CT + cc] = make_float2(t0, 0.0f);
                spec[(8 * PP + s) * CT + cc] = make_float2(t8, 0.0f);
            }
        } else {
            int v = vg;
            uint64_t T[16];
#pragma unroll
            for (int s = 0; s < 16; s++) T[s] = pack2(0.0f, 0.0f);
#pragma unroll
            for (int p = 0; p < 16; p++) {
                float2 X = spec[(v * PP + p) * CT + cc];
                uint64_t XP = pack2(X.x, X.y);
                uint64_t XS = pack2(X.y, X.x);
#pragma unroll
                for (int s = 0; s < 16; s++) {
                    int d = (s - p) & 15;
                    T[s] = fma2(muA[d], XP, T[s]);
                    T[s] = fma2(muB[d], XS, T[s]);
                }
            }
#pragma unroll
            for (int s = 0; s < 16; s++) {
                float tx, ty;
                unpack2(T[s], tx, ty);
                spec[(v * PP + s) * CT + cc] = make_float2(tx, ty);
            }
        }
        __syncthreads();

        // ---- Phase 3: inverse column pass, radix-2 folded, rows r and r+8 ----
#pragma unroll
        for (int row = 0; row < 2; row++) {
            int rr = r + row * 8;
            float2 Tv[NV];
#pragma unroll
            for (int v = 0; v < NV; v++) Tv[v] = spec[(v * PP + rr) * CT + c];

            float* op = out + ((size_t)(b * 256 + rr * 16) * CCH + c0 + c);
#pragma unroll
            for (int t = 0; t < 8; t++) {
                // even v contribution (v=0,2,4,6,8) ; odd (1,3,5,7)
                float ge = Tv[0].x;                 // C16(0)=1, S=0, Tv0.y==0
                ge = fmaf(Tv[8].x, C16(8 * t), ge); // +/-1, Tv8.y==0
#pragma unroll
                for (int v = 2; v < 8; v += 2) {
                    ge = fmaf(Tv[v].x,  C16(v * t), ge);
                    ge = fmaf(Tv[v].y, -S16(v * t), ge);
                }
                float go = 0.0f;
#pragma unroll
                for (int v = 1; v < 8; v += 2) {
                    go = fmaf(Tv[v].x,  C16(v * t), go);
                    go = fmaf(Tv[v].y, -S16(v * t), go);
                }
                op[(size_t)t * CCH]       = ge + go;
                op[(size_t)(t + 8) * CCH] = ge - go;
            }
        }
        __syncthreads();   // spec reused by next batch's phase 1
    }
}

// ---------------------------------------------------------------------------
extern "C" void kernel_launch(void* const* d_in, const int* in_sizes, int n_in,
                              void* d_out, int out_size) {
    const float* x = (const float*)d_in[0];
    const float* w = (const float*)d_in[1];
    float* out     = (float*)d_out;
    (void)in_sizes; (void)n_in; (void)out_size;

    gf_prep<<<(CCH * NV * PP + 255) / 256, 256>>>(w);

    dim3 grid(NCT, 64);
    gf_main<<<grid, 256>>>(x, out);
}

// round 4
// speedup vs baseline: 2.2819x; 1.1780x over previous
#include <cuda_runtime.h>
#include <cstdint>

// GlobalFilter: out = irfft2( rfft2(x,ortho) * W, ortho ), 16x16 spatial, per channel.
//   Ph1: column rDFT over t (radix-2 folded)                 thread=(c32, 2 rows)
//   Ph2: per-(c,v) row circular conv via 16-pt FFT +         thread=(c32, vgroup)
//        pointwise W-multiply + IFFT  (v=1..7 complex;
//        v={0,8} packed real dense conv)
//   Ph3: inverse column pass (radix-2 folded)                thread=(c32, 2 rows)
//
// x: [128,256,768] f32 ; W: [16,9,768,2] f32 ; out: [128,256,768] f32

#define PP    16
#define NV    9
#define CT    32
#define CCH   768
#define NCT   (CCH / CT)   // 24

// real taps for v=0 / v=8 dense conv: [ct][d][c32] -> (mu0, mu8)*scale
__device__ float2 g_muR[NCT * PP * CT];
// freq-domain filter for v=1..7, BIT-REVERSED u order, scale 1/128:
// [ct][v-1][i][c32] -> (re, im)
__device__ float2 g_Wh[NCT * 7 * PP * CT];

__constant__ float d_COS16[16] = {
    1.0f,  0.9238795325112867f,  0.7071067811865476f,  0.3826834323650898f,
    0.0f, -0.3826834323650898f, -0.7071067811865476f, -0.9238795325112867f,
   -1.0f, -0.9238795325112867f, -0.7071067811865476f, -0.3826834323650898f,
    0.0f,  0.3826834323650898f,  0.7071067811865476f,  0.9238795325112867f};
__constant__ float d_SIN16[16] = {
    0.0f,  0.3826834323650898f,  0.7071067811865476f,  0.9238795325112867f,
    1.0f,  0.9238795325112867f,  0.7071067811865476f,  0.3826834323650898f,
    0.0f, -0.3826834323650898f, -0.7071067811865476f, -0.9238795325112867f,
   -1.0f, -0.9238795325112867f, -0.7071067811865476f, -0.3826834323650898f};

__host__ __device__ __forceinline__ constexpr float C16(int k) {
    return (k % 16 == 0)  ?  1.0f :
           (k % 16 == 1)  ?  0.9238795325112867f :
           (k % 16 == 2)  ?  0.7071067811865476f :
           (k % 16 == 3)  ?  0.3826834323650898f :
           (k % 16 == 4)  ?  0.0f :
           (k % 16 == 5)  ? -0.3826834323650898f :
           (k % 16 == 6)  ? -0.7071067811865476f :
           (k % 16 == 7)  ? -0.9238795325112867f :
           (k % 16 == 8)  ? -1.0f :
           (k % 16 == 9)  ? -0.9238795325112867f :
           (k % 16 == 10) ? -0.7071067811865476f :
           (k % 16 == 11) ? -0.3826834323650898f :
           (k % 16 == 12) ?  0.0f :
           (k % 16 == 13) ?  0.3826834323650898f :
           (k % 16 == 14) ?  0.7071067811865476f :
                             0.9238795325112867f;
}
__host__ __device__ __forceinline__ constexpr float S16(int k) {
    return C16(k % 16 + 12);
}
__host__ __device__ __forceinline__ constexpr int REV4(int i) {
    return ((i & 1) << 3) | ((i & 2) << 1) | ((i & 4) >> 1) | ((i & 8) >> 3);
}

// a+b / a-b as FFMA-imm (rt=1 on SMSP vs rt=2 for FADD)
__device__ __forceinline__ float fadd1(float a, float b) {
    float r; asm("fma.rn.f32 %0, %1, 0f3F800000, %2;" : "=f"(r) : "f"(a), "f"(b)); return r;
}
__device__ __forceinline__ float fsub1(float a, float b) {  // a - b
    float r; asm("fma.rn.f32 %0, %1, 0fBF800000, %2;" : "=f"(r) : "f"(b), "f"(a)); return r;
}

__device__ __forceinline__ uint64_t pack2(float lo, float hi) {
    uint64_t r; asm("mov.b64 %0, {%1, %2};" : "=l"(r) : "f"(lo), "f"(hi)); return r;
}
__device__ __forceinline__ void unpack2(uint64_t v, float& lo, float& hi) {
    asm("mov.b64 {%0, %1}, %2;" : "=f"(lo), "=f"(hi) : "l"(v));
}
__device__ __forceinline__ uint64_t fma2(uint64_t a, uint64_t b, uint64_t c) {
    uint64_t r; asm("fma.rn.f32x2 %0, %1, %2, %3;" : "=l"(r) : "l"(a), "l"(b), "l"(c)); return r;
}

// complex butterfly: (a,b) -> (a+b, a-b)
__device__ __forceinline__ void bfly(float& ar, float& ai, float& br, float& bi) {
    float sr = fadd1(ar, br), si = fadd1(ai, bi);
    float dr = fsub1(ar, br), di = fsub1(ai, bi);
    ar = sr; ai = si; br = dr; bi = di;
}
// multiply by e^{-2*pi*i*K/16}
template<int K> __device__ __forceinline__ void twf(float& re, float& im) {
    constexpr int k = ((K) % 16 + 16) % 16;
    if constexpr (k == 0) { }
    else if constexpr (k == 4)  { float t = re; re = im;  im = -t; }
    else if constexpr (k == 8)  { re = -re; im = -im; }
    else if constexpr (k == 12) { float t = re; re = -im; im = t;  }
    else {
        constexpr float cs = C16(k), sn = S16(k);
        float nr = fmaf(im,  sn, re * cs);
        float ni = fmaf(re, -sn, im * cs);
        re = nr; im = ni;
    }
}
// multiply by e^{+2*pi*i*K/16}
template<int K> __device__ __forceinline__ void twi(float& re, float& im) {
    constexpr int k = ((K) % 16 + 16) % 16;
    if constexpr (k == 0) { }
    else if constexpr (k == 4)  { float t = re; re = -im; im = t;  }
    else if constexpr (k == 8)  { re = -re; im = -im; }
    else if constexpr (k == 12) { float t = re; re = im;  im = -t; }
    else {
        constexpr float cs = C16(k), sn = S16(k);
        float nr = fmaf(im, -sn, re * cs);
        float ni = fmaf(re,  sn, im * cs);
        re = nr; im = ni;
    }
}

// 16-pt DIF forward FFT, natural in -> bit-reversed out
__device__ __forceinline__ void fft16_fwd(float* Xr, float* Xi) {
#pragma unroll
    for (int j = 0; j < 8; j++) { bfly(Xr[j], Xi[j], Xr[j+8], Xi[j+8]); }
    twf<1>(Xr[9],Xi[9]);  twf<2>(Xr[10],Xi[10]); twf<3>(Xr[11],Xi[11]);
    twf<4>(Xr[12],Xi[12]); twf<5>(Xr[13],Xi[13]); twf<6>(Xr[14],Xi[14]); twf<7>(Xr[15],Xi[15]);
#pragma unroll
    for (int h = 0; h < 2; h++) {
        int o = h * 8;
#pragma unroll
        for (int j = 0; j < 4; j++) bfly(Xr[o+j], Xi[o+j], Xr[o+j+4], Xi[o+j+4]);
        twf<2>(Xr[o+5],Xi[o+5]); twf<4>(Xr[o+6],Xi[o+6]); twf<6>(Xr[o+7],Xi[o+7]);
    }
#pragma unroll
    for (int q = 0; q < 4; q++) {
        int o = q * 4;
        bfly(Xr[o], Xi[o], Xr[o+2], Xi[o+2]);
        bfly(Xr[o+1], Xi[o+1], Xr[o+3], Xi[o+3]);
        twf<4>(Xr[o+3], Xi[o+3]);
    }
#pragma unroll
    for (int p = 0; p < 8; p++) bfly(Xr[2*p], Xi[2*p], Xr[2*p+1], Xi[2*p+1]);
}

// 16-pt DIT inverse FFT (unscaled), bit-reversed in -> natural out
__device__ __forceinline__ void fft16_inv(float* Xr, float* Xi) {
#pragma unroll
    for (int p = 0; p < 8; p++) bfly(Xr[2*p], Xi[2*p], Xr[2*p+1], Xi[2*p+1]);
#pragma unroll
    for (int q = 0; q < 4; q++) {
        int o = q * 4;
        twi<4>(Xr[o+3], Xi[o+3]);
        bfly(Xr[o], Xi[o], Xr[o+2], Xi[o+2]);
        bfly(Xr[o+1], Xi[o+1], Xr[o+3], Xi[o+3]);
    }
#pragma unroll
    for (int h = 0; h < 2; h++) {
        int o = h * 8;
        twi<2>(Xr[o+5],Xi[o+5]); twi<4>(Xr[o+6],Xi[o+6]); twi<6>(Xr[o+7],Xi[o+7]);
#pragma unroll
        for (int j = 0; j < 4; j++) bfly(Xr[o+j], Xi[o+j], Xr[o+j+4], Xi[o+j+4]);
    }
    twi<1>(Xr[9],Xi[9]);  twi<2>(Xr[10],Xi[10]); twi<3>(Xr[11],Xi[11]);
    twi<4>(Xr[12],Xi[12]); twi<5>(Xr[13],Xi[13]); twi<6>(Xr[14],Xi[14]); twi<7>(Xr[15],Xi[15]);
#pragma unroll
    for (int j = 0; j < 8; j++) bfly(Xr[j], Xi[j], Xr[j+8], Xi[j+8]);
}

// ---------------------------------------------------------------------------
// K1 prep: v in {0,8} -> dense spatial taps muR; v in 1..7 -> scaled W in
// bit-reversed u order.
// ---------------------------------------------------------------------------
__global__ void gf_prep(const float* __restrict__ w) {
    int tid = blockIdx.x * blockDim.x + threadIdx.x;
    if (tid >= CCH * NV * PP) return;
    int c   = tid / (NV * PP);
    int rem = tid - c * (NV * PP);
    int v   = rem / PP;
    int d   = rem - v * PP;     // d for v0/v8 ; u for v=1..7
    int ct  = c >> 5;
    int cl  = c & (CT - 1);

    if (v == 0 || v == 8) {
        float re = 0.0f;
#pragma unroll
        for (int u = 0; u < 16; u++) {
            int iw   = ((u * NV + v) * CCH + c) * 2;
            float wr = w[iw];
            float wi = w[iw + 1];
            int k    = (u * d) & 15;
            re = fmaf(wr, d_COS16[k], fmaf(-wi, d_SIN16[k], re));
        }
        if (v == 0) g_muR[(ct * PP + d) * CT + cl].x = re * (1.0f / 256.0f);
        else        g_muR[(ct * PP + d) * CT + cl].y = re * (1.0f / 256.0f);
    } else {
        int u  = d;
        int iw = ((u * NV + v) * CCH + c) * 2;
        int i  = REV4(u);
        g_Wh[((ct * 7 + (v - 1)) * PP + i) * CT + cl] =
            make_float2(w[iw] * (1.0f / 128.0f), w[iw + 1] * (1.0f / 128.0f));
    }
}

// ---------------------------------------------------------------------------
// K2: block 256 thr, grid (24 c-tiles, 64 batch-pairs), 2 batches per block
// ---------------------------------------------------------------------------
__global__ void __launch_bounds__(256, 3) gf_main(const float* __restrict__ x,
                                                  float* __restrict__ out) {
    __shared__ float2 spec[NV * PP * CT];   // [v][p][c32], reused in-place

    int tid = threadIdx.x;
    int c   = tid & (CT - 1);
    int r   = tid >> 5;                     // 0..7
    int c0  = blockIdx.x * CT;
    int cc  = c;
    int vg  = r;                            // 0 -> packed real (v0,v8); 1..7 -> FFT conv

    // --- preload per-thread filter data (reused for both batches) ---
    uint64_t muA[16];                       // vg==0 only
    float Whr[16], Whi[16];                 // vg!=0 only
    if (vg == 0) {
        const uint64_t* mR = reinterpret_cast<const uint64_t*>(g_muR)
                           + (blockIdx.x * PP) * CT + cc;
#pragma unroll
        for (int d = 0; d < 16; d++) muA[d] = mR[d * CT];
    } else {
        const float2* wh = g_Wh + ((blockIdx.x * 7 + vg - 1) * PP) * CT + cc;
#pragma unroll
        for (int i = 0; i < 16; i++) { float2 t = wh[i * CT]; Whr[i] = t.x; Whi[i] = t.y; }
    }

    for (int bi = 0; bi < 2; bi++) {
        int b = blockIdx.y * 2 + bi;

        // ---- Phase 1: column rDFT over t, radix-2 folded, rows r and r+8 ----
#pragma unroll
        for (int row = 0; row < 2; row++) {
            int rr = r + row * 8;
            float xr[16];
            const float* xp = x + ((size_t)(b * 256 + rr * 16) * CCH + c0 + c);
#pragma unroll
            for (int t = 0; t < 16; t++) xr[t] = xp[(size_t)t * CCH];

            float s[8], dd[8];
#pragma unroll
            for (int t = 0; t < 8; t++) { s[t] = fadd1(xr[t], xr[t+8]); dd[t] = fsub1(xr[t], xr[t+8]); }
            {
                float a = fadd1(fadd1(s[0], s[1]), fadd1(s[2], s[3]));
                float bb= fadd1(fadd1(s[4], s[5]), fadd1(s[6], s[7]));
                spec[(0 * PP + rr) * CT + c] = make_float2(fadd1(a, bb), 0.0f);
            }
            {
                float a = fadd1(fsub1(s[0], s[1]), fsub1(s[2], s[3]));
                float bb= fadd1(fsub1(s[4], s[5]), fsub1(s[6], s[7]));
                spec[(8 * PP + rr) * CT + c] = make_float2(fadd1(a, bb), 0.0f);
            }
#pragma unroll
            for (int v = 1; v < 8; v++) {
                const float* src = (v & 1) ? dd : s;
                float re = 0.0f, im = 0.0f;
#pragma unroll
                for (int t = 0; t < 8; t++) {
                    re = fmaf(src[t],  C16(v * t), re);
                    im = fmaf(src[t], -S16(v * t), im);
                }
                spec[(v * PP + rr) * CT + c] = make_float2(re, im);
            }
        }
        __syncthreads();

        // ---- Phase 2 ----
        if (vg == 0) {
            // packed real dense conv for v=0 (lo) and v=8 (hi)
            uint64_t T[16];
#pragma unroll
            for (int s = 0; s < 16; s++) T[s] = pack2(0.0f, 0.0f);
#pragma unroll
            for (int p = 0; p < 16; p++) {
                float x0 = spec[(0 * PP + p) * CT + cc].x;
                float x8 = spec[(8 * PP + p) * CT + cc].x;
                uint64_t XR = pack2(x0, x8);
#pragma unroll
                for (int s = 0; s < 16; s++)
                    T[s] = fma2(muA[(s - p) & 15], XR, T[s]);
            }
#pragma unroll
            for (int s = 0; s < 16; s++) {
                float t0, t8;
                unpack2(T[s], t0, t8);
                spec[(0 * PP + s) * CT + cc] = make_float2(t0, 0.0f);
                spec[(8 * PP + s) * CT + cc] = make_float2(t8, 0.0f);
            }
        } else {
            int v = vg;
            float Xr[16], Xi[16];
#pragma unroll
            for (int p = 0; p < 16; p++) {
                float2 t = spec[(v * PP + p) * CT + cc];
                Xr[p] = t.x; Xi[p] = t.y;
            }
            fft16_fwd(Xr, Xi);
#pragma unroll
            for (int i = 0; i < 16; i++) {
                float nr = fmaf(-Xi[i], Whi[i], Xr[i] * Whr[i]);
                float ni = fmaf( Xi[i], Whr[i], Xr[i] * Whi[i]);
                Xr[i] = nr; Xi[i] = ni;
            }
            fft16_inv(Xr, Xi);
#pragma unroll
            for (int s = 0; s < 16; s++)
                spec[(v * PP + s) * CT + cc] = make_float2(Xr[s], Xi[s]);
        }
        __syncthreads();

        // ---- Phase 3: inverse column pass, radix-2 folded ----
#pragma unroll
        for (int row = 0; row < 2; row++) {
            int rr = r + row * 8;
            float2 Tv[NV];
#pragma unroll
            for (int v = 0; v < NV; v++) Tv[v] = spec[(v * PP + rr) * CT + c];

            float* op = out + ((size_t)(b * 256 + rr * 16) * CCH + c0 + c);
#pragma unroll
            for (int t = 0; t < 8; t++) {
                float ge = Tv[0].x;
                ge = fmaf(Tv[8].x, C16(8 * t), ge);
#pragma unroll
                for (int v = 2; v < 8; v += 2) {
                    ge = fmaf(Tv[v].x,  C16(v * t), ge);
                    ge = fmaf(Tv[v].y, -S16(v * t), ge);
                }
                float go = 0.0f;
#pragma unroll
                for (int v = 1; v < 8; v += 2) {
                    go = fmaf(Tv[v].x,  C16(v * t), go);
                    go = fmaf(Tv[v].y, -S16(v * t), go);
                }
                op[(size_t)t * CCH]       = fadd1(ge, go);
                op[(size_t)(t + 8) * CCH] = fsub1(ge, go);
            }
        }
        __syncthreads();   // spec reused by next batch's phase 1
    }
}

// ---------------------------------------------------------------------------
extern "C" void kernel_launch(void* const* d_in, const int* in_sizes, int n_in,
                              void* d_out, int out_size) {
    const float* x = (const float*)d_in[0];
    const float* w = (const float*)d_in[1];
    float* out     = (float*)d_out;
    (void)in_sizes; (void)n_in; (void)out_size;

    gf_prep<<<(CCH * NV * PP + 255) / 256, 256>>>(w);

    dim3 grid(NCT, 64);
    gf_main<<<grid, 256>>>(x, out);
}

// round 5
// speedup vs baseline: 2.4812x; 1.0873x over previous
#include <cuda_runtime.h>
#include <cstdint>

// GlobalFilter: out = irfft2( rfft2(x,ortho) * W, ortho ), 16x16 spatial, per channel.
//   Ph1: column rDFT over t (radix-2 folded)                 thread=(c32, 2 rows)
//   Ph2: per-(c,v) row circular conv via 16-pt FFT +         thread=(c32, vgroup)
//        pointwise W-multiply + IFFT  (v=1..7 complex;
//        v={0,8} packed real dense conv, two-half)
//   Ph3: inverse column pass (radix-2 folded)                thread=(c32, 2 rows)
//
// x: [128,256,768] f32 ; W: [16,9,768,2] f32 ; out: [128,256,768] f32

#define PP    16
#define NV    9
#define CT    32
#define CCH   768
#define NCT   (CCH / CT)   // 24

// real taps for v=0 / v=8 dense conv: [ct][d][c32] -> (mu0, mu8)*1/256
__device__ float2 g_muR[NCT * PP * CT];
// freq-domain filter for v=1..7, BIT-REVERSED u order, scale 1/128:
// [ct][v-1][i][c32] -> (re, im)
__device__ float2 g_Wh[NCT * 7 * PP * CT];

__host__ __device__ __forceinline__ constexpr float C16(int k) {
    return (k % 16 == 0)  ?  1.0f :
           (k % 16 == 1)  ?  0.9238795325112867f :
           (k % 16 == 2)  ?  0.7071067811865476f :
           (k % 16 == 3)  ?  0.3826834323650898f :
           (k % 16 == 4)  ?  0.0f :
           (k % 16 == 5)  ? -0.3826834323650898f :
           (k % 16 == 6)  ? -0.7071067811865476f :
           (k % 16 == 7)  ? -0.9238795325112867f :
           (k % 16 == 8)  ? -1.0f :
           (k % 16 == 9)  ? -0.9238795325112867f :
           (k % 16 == 10) ? -0.7071067811865476f :
           (k % 16 == 11) ? -0.3826834323650898f :
           (k % 16 == 12) ?  0.0f :
           (k % 16 == 13) ?  0.3826834323650898f :
           (k % 16 == 14) ?  0.7071067811865476f :
                             0.9238795325112867f;
}
__host__ __device__ __forceinline__ constexpr float S16(int k) {
    return C16(k % 16 + 12);
}
__host__ __device__ __forceinline__ constexpr int REV4(int i) {
    return ((i & 1) << 3) | ((i & 2) << 1) | ((i & 4) >> 1) | ((i & 8) >> 3);
}

// a+b / a-b as FFMA-imm (rt=1 vs rt=2 for FADD)
__device__ __forceinline__ float fadd1(float a, float b) {
    float r; asm("fma.rn.f32 %0, %1, 0f3F800000, %2;" : "=f"(r) : "f"(a), "f"(b)); return r;
}
__device__ __forceinline__ float fsub1(float a, float b) {  // a - b
    float r; asm("fma.rn.f32 %0, %1, 0fBF800000, %2;" : "=f"(r) : "f"(b), "f"(a)); return r;
}

__device__ __forceinline__ uint64_t pack2(float lo, float hi) {
    uint64_t r; asm("mov.b64 %0, {%1, %2};" : "=l"(r) : "f"(lo), "f"(hi)); return r;
}
__device__ __forceinline__ void unpack2(uint64_t v, float& lo, float& hi) {
    asm("mov.b64 {%0, %1}, %2;" : "=f"(lo), "=f"(hi) : "l"(v));
}
__device__ __forceinline__ uint64_t fma2(uint64_t a, uint64_t b, uint64_t c) {
    uint64_t r; asm("fma.rn.f32x2 %0, %1, %2, %3;" : "=l"(r) : "l"(a), "l"(b), "l"(c)); return r;
}

// complex butterfly: (a,b) -> (a+b, a-b)
__device__ __forceinline__ void bfly(float& ar, float& ai, float& br, float& bi) {
    float sr = fadd1(ar, br), si = fadd1(ai, bi);
    float dr = fsub1(ar, br), di = fsub1(ai, bi);
    ar = sr; ai = si; br = dr; bi = di;
}
// multiply by e^{-2*pi*i*K/16}
template<int K> __device__ __forceinline__ void twf(float& re, float& im) {
    constexpr int k = ((K) % 16 + 16) % 16;
    if constexpr (k == 0) { }
    else if constexpr (k == 4)  { float t = re; re = im;  im = -t; }
    else if constexpr (k == 8)  { re = -re; im = -im; }
    else if constexpr (k == 12) { float t = re; re = -im; im = t;  }
    else {
        constexpr float cs = C16(k), sn = S16(k);
        float nr = fmaf(im,  sn, re * cs);
        float ni = fmaf(re, -sn, im * cs);
        re = nr; im = ni;
    }
}
// multiply by e^{+2*pi*i*K/16}
template<int K> __device__ __forceinline__ void twi(float& re, float& im) {
    constexpr int k = ((K) % 16 + 16) % 16;
    if constexpr (k == 0) { }
    else if constexpr (k == 4)  { float t = re; re = -im; im = t;  }
    else if constexpr (k == 8)  { re = -re; im = -im; }
    else if constexpr (k == 12) { float t = re; re = im;  im = -t; }
    else {
        constexpr float cs = C16(k), sn = S16(k);
        float nr = fmaf(im, -sn, re * cs);
        float ni = fmaf(re,  sn, im * cs);
        re = nr; im = ni;
    }
}

// 16-pt DIF forward FFT, natural in -> bit-reversed out
__device__ __forceinline__ void fft16_fwd(float* Xr, float* Xi) {
#pragma unroll
    for (int j = 0; j < 8; j++) { bfly(Xr[j], Xi[j], Xr[j+8], Xi[j+8]); }
    twf<1>(Xr[9],Xi[9]);  twf<2>(Xr[10],Xi[10]); twf<3>(Xr[11],Xi[11]);
    twf<4>(Xr[12],Xi[12]); twf<5>(Xr[13],Xi[13]); twf<6>(Xr[14],Xi[14]); twf<7>(Xr[15],Xi[15]);
#pragma unroll
    for (int h = 0; h < 2; h++) {
        int o = h * 8;
#pragma unroll
        for (int j = 0; j < 4; j++) bfly(Xr[o+j], Xi[o+j], Xr[o+j+4], Xi[o+j+4]);
        twf<2>(Xr[o+5],Xi[o+5]); twf<4>(Xr[o+6],Xi[o+6]); twf<6>(Xr[o+7],Xi[o+7]);
    }
#pragma unroll
    for (int q = 0; q < 4; q++) {
        int o = q * 4;
        bfly(Xr[o], Xi[o], Xr[o+2], Xi[o+2]);
        bfly(Xr[o+1], Xi[o+1], Xr[o+3], Xi[o+3]);
        twf<4>(Xr[o+3], Xi[o+3]);
    }
#pragma unroll
    for (int p = 0; p < 8; p++) bfly(Xr[2*p], Xi[2*p], Xr[2*p+1], Xi[2*p+1]);
}

// 16-pt DIT inverse FFT (unscaled), bit-reversed in -> natural out
__device__ __forceinline__ void fft16_inv(float* Xr, float* Xi) {
#pragma unroll
    for (int p = 0; p < 8; p++) bfly(Xr[2*p], Xi[2*p], Xr[2*p+1], Xi[2*p+1]);
#pragma unroll
    for (int q = 0; q < 4; q++) {
        int o = q * 4;
        twi<4>(Xr[o+3], Xi[o+3]);
        bfly(Xr[o], Xi[o], Xr[o+2], Xi[o+2]);
        bfly(Xr[o+1], Xi[o+1], Xr[o+3], Xi[o+3]);
    }
#pragma unroll
    for (int h = 0; h < 2; h++) {
        int o = h * 8;
        twi<2>(Xr[o+5],Xi[o+5]); twi<4>(Xr[o+6],Xi[o+6]); twi<6>(Xr[o+7],Xi[o+7]);
#pragma unroll
        for (int j = 0; j < 4; j++) bfly(Xr[o+j], Xi[o+j], Xr[o+j+4], Xi[o+j+4]);
    }
    twi<1>(Xr[9],Xi[9]);  twi<2>(Xr[10],Xi[10]); twi<3>(Xr[11],Xi[11]);
    twi<4>(Xr[12],Xi[12]); twi<5>(Xr[13],Xi[13]); twi<6>(Xr[14],Xi[14]); twi<7>(Xr[15],Xi[15]);
#pragma unroll
    for (int j = 0; j < 8; j++) bfly(Xr[j], Xi[j], Xr[j+8], Xi[j+8]);
}

// ---------------------------------------------------------------------------
// K1 prep (single kernel, no trig tables):
//   tid <  86016 : scaled copy of W (v=1..7) into bit-reversed g_Wh
//   tid >= 86016 : register IFFT to build spatial taps muR for v in {0,8}
// ---------------------------------------------------------------------------
#define T_COPY (NCT * 7 * PP * CT)   // 86016
#define T_TAPS (CCH * 2)             // 1536

__global__ void gf_prep(const float* __restrict__ w) {
    int tid = blockIdx.x * blockDim.x + threadIdx.x;
    if (tid < T_COPY) {
        int cl   = tid & (CT - 1);
        int rest = tid >> 5;
        int u    = rest & 15;
        int rest2= rest >> 4;
        int vm1  = rest2 % 7;
        int ct   = rest2 / 7;
        int c    = ct * CT + cl;
        int v    = vm1 + 1;
        int iw   = ((u * NV + v) * CCH + c) * 2;
        g_Wh[((ct * 7 + vm1) * PP + REV4(u)) * CT + cl] =
            make_float2(w[iw] * (1.0f / 128.0f), w[iw + 1] * (1.0f / 128.0f));
    } else if (tid < T_COPY + T_TAPS) {
        int t2   = tid - T_COPY;
        int vsel = t2 & 1;              // 0 -> v=0, 1 -> v=8
        int c    = t2 >> 1;
        int v    = vsel ? 8 : 0;
        float Zr[16], Zi[16];
#pragma unroll
        for (int u = 0; u < 16; u++) {
            int iw = ((u * NV + v) * CCH + c) * 2;
            int i  = REV4(u);
            Zr[i] = w[iw];
            Zi[i] = w[iw + 1];
        }
        fft16_inv(Zr, Zi);              // y[d] = sum_u W[u] e^{+2 pi i u d/16}
        int ct = c >> 5;
        int cl = c & (CT - 1);
#pragma unroll
        for (int d = 0; d < 16; d++) {
            float* dst = &g_muR[(ct * PP + d) * CT + cl].x;
            dst[vsel] = Zr[d] * (1.0f / 256.0f);
        }
    }
}

// ---------------------------------------------------------------------------
// K2: block 256 thr, grid (24 c-tiles, 64 batch-pairs), 2 batches per block
// All filter data loaded on demand inside phase 2 (L1/L2-resident) to keep
// register count <= 64 for 4 CTAs/SM.
// ---------------------------------------------------------------------------
__global__ void __launch_bounds__(256, 4) gf_main(const float* __restrict__ x,
                                                  float* __restrict__ out) {
    __shared__ float2 spec[NV * PP * CT];   // [v][p][c32], reused in-place

    int tid = threadIdx.x;
    int c   = tid & (CT - 1);
    int r   = tid >> 5;                     // 0..7
    int c0  = blockIdx.x * CT;
    int cc  = c;
    int vg  = r;                            // 0 -> packed real (v0,v8); 1..7 -> FFT conv

#pragma unroll 1
    for (int bi = 0; bi < 2; bi++) {
        int b = blockIdx.y * 2 + bi;

        // ---- Phase 1: column rDFT over t, radix-2 folded, rows r and r+8 ----
#pragma unroll
        for (int row = 0; row < 2; row++) {
            int rr = r + row * 8;
            float xr[16];
            const float* xp = x + ((size_t)(b * 256 + rr * 16) * CCH + c0 + c);
#pragma unroll
            for (int t = 0; t < 16; t++) xr[t] = xp[(size_t)t * CCH];

            float s[8], dd[8];
#pragma unroll
            for (int t = 0; t < 8; t++) { s[t] = fadd1(xr[t], xr[t+8]); dd[t] = fsub1(xr[t], xr[t+8]); }
            {
                float a = fadd1(fadd1(s[0], s[1]), fadd1(s[2], s[3]));
                float bb= fadd1(fadd1(s[4], s[5]), fadd1(s[6], s[7]));
                spec[(0 * PP + rr) * CT + c].x = fadd1(a, bb);
            }
            {
                float a = fadd1(fsub1(s[0], s[1]), fsub1(s[2], s[3]));
                float bb= fadd1(fsub1(s[4], s[5]), fsub1(s[6], s[7]));
                spec[(8 * PP + rr) * CT + c].x = fadd1(a, bb);
            }
#pragma unroll
            for (int v = 1; v < 8; v++) {
                const float* src = (v & 1) ? dd : s;
                float re = 0.0f, im = 0.0f;
#pragma unroll
                for (int t = 0; t < 8; t++) {
                    re = fmaf(src[t],  C16(v * t), re);
                    im = fmaf(src[t], -S16(v * t), im);
                }
                spec[(v * PP + rr) * CT + c] = make_float2(re, im);
            }
        }
        __syncthreads();

        // ---- Phase 2 ----
        if (vg == 0) {
            // packed real dense conv for v=0 (lo) and v=8 (hi),
            // two halves of 8 outputs; results go to the .y slots so the
            // .x inputs stay intact for the second half.
            uint64_t muA[16];
            {
                const uint64_t* mR = reinterpret_cast<const uint64_t*>(g_muR)
                                   + (blockIdx.x * PP) * CT + cc;
#pragma unroll
                for (int d = 0; d < 16; d++) muA[d] = mR[d * CT];
            }
#pragma unroll
            for (int half = 0; half < 2; half++) {
                uint64_t T[8];
#pragma unroll
                for (int s8 = 0; s8 < 8; s8++) T[s8] = pack2(0.0f, 0.0f);
#pragma unroll
                for (int p = 0; p < 16; p++) {
                    float x0 = spec[(0 * PP + p) * CT + cc].x;
                    float x8 = spec[(8 * PP + p) * CT + cc].x;
                    uint64_t XR = pack2(x0, x8);
#pragma unroll
                    for (int s8 = 0; s8 < 8; s8++) {
                        int s = half * 8 + s8;
                        T[s8] = fma2(muA[(s - p) & 15], XR, T[s8]);
                    }
                }
#pragma unroll
                for (int s8 = 0; s8 < 8; s8++) {
                    int s = half * 8 + s8;
                    float t0, t8;
                    unpack2(T[s8], t0, t8);
                    spec[(0 * PP + s) * CT + cc].y = t0;
                    spec[(8 * PP + s) * CT + cc].y = t8;
                }
            }
        } else {
            int v = vg;
            float Xr[16], Xi[16];
#pragma unroll
            for (int p = 0; p < 16; p++) {
                float2 t = spec[(v * PP + p) * CT + cc];
                Xr[p] = t.x; Xi[p] = t.y;
            }
            fft16_fwd(Xr, Xi);
            {
                const float2* wh = g_Wh + ((blockIdx.x * 7 + v - 1) * PP) * CT + cc;
#pragma unroll
                for (int i = 0; i < 16; i++) {
                    float2 W = wh[i * CT];
                    float nr = fmaf(-Xi[i], W.y, Xr[i] * W.x);
                    float ni = fmaf( Xi[i], W.x, Xr[i] * W.y);
                    Xr[i] = nr; Xi[i] = ni;
                }
            }
            fft16_inv(Xr, Xi);
#pragma unroll
            for (int s = 0; s < 16; s++)
                spec[(v * PP + s) * CT + cc] = make_float2(Xr[s], Xi[s]);
        }
        __syncthreads();

        // ---- Phase 3: inverse column pass, radix-2 folded ----
        // v0/v8 results live in the .y slots; v=1..7 are full complex.
#pragma unroll
        for (int row = 0; row < 2; row++) {
            int rr = r + row * 8;
            float tv0 = spec[(0 * PP + rr) * CT + c].y;
            float tv8 = spec[(8 * PP + rr) * CT + c].y;
            float2 Tv[8];
#pragma unroll
            for (int v = 1; v < 8; v++) Tv[v] = spec[(v * PP + rr) * CT + c];

            float* op = out + ((size_t)(b * 256 + rr * 16) * CCH + c0 + c);
#pragma unroll
            for (int t = 0; t < 8; t++) {
                float ge = tv0;
                ge = fmaf(tv8, C16(8 * t), ge);
#pragma unroll
                for (int v = 2; v < 8; v += 2) {
                    ge = fmaf(Tv[v].x,  C16(v * t), ge);
                    ge = fmaf(Tv[v].y, -S16(v * t), ge);
                }
                float go = 0.0f;
#pragma unroll
                for (int v = 1; v < 8; v += 2) {
                    go = fmaf(Tv[v].x,  C16(v * t), go);
                    go = fmaf(Tv[v].y, -S16(v * t), go);
                }
                op[(size_t)t * CCH]       = fadd1(ge, go);
                op[(size_t)(t + 8) * CCH] = fsub1(ge, go);
            }
        }
        __syncthreads();   // spec reused by next batch's phase 1
    }
}

// ---------------------------------------------------------------------------
extern "C" void kernel_launch(void* const* d_in, const int* in_sizes, int n_in,
                              void* d_out, int out_size) {
    const float* x = (const float*)d_in[0];
    const float* w = (const float*)d_in[1];
    float* out     = (float*)d_out;
    (void)in_sizes; (void)n_in; (void)out_size;

    gf_prep<<<(T_COPY + T_TAPS + 255) / 256, 256>>>(w);

    dim3 grid(NCT, 64);
    gf_main<<<grid, 256>>>(x, out);
}